// round 12
// baseline (speedup 1.0000x reference)
#include <cuda_runtime.h>
#include <cooperative_groups.h>

namespace cg = cooperative_groups;

// y[b,c] = b_fc[c] + sum_f h[b,0,f] * V[c,f],  V = W_fc @ W_emb  ([2,768])
// (TreeLSTM scan in the reference is dead code; adj and recurrent weights unused.)
// B=32, N=128, FI=768, FO=128.
//
// ONE node, 16-CTA cluster (nonportable size: attribute set host-side once),
// f-partitioned (48 f per CTA => 30 KB stream/SM). PUSH-model reduction:
// every CTA stores its 64 partial y's into rank 0's smem (DSMEM ST, latency
// not exposed), ONE cluster.sync (arrive.release orders the stores), rank 0
// sums from its OWN smem and writes y.

#define B_   32
#define N_   128
#define FI_  768
#define FO_  128
#define CSZ  16         // cluster size (nonportable, needs attribute)
#define FS   (FI_/CSZ)  // 48 f per CTA
#define FQ   (FS/4)     // 12 quads per CTA
#define NOG  32         // o-groups (4 o's each)
#define NT   (NOG*FQ)   // 384 threads

__global__ __launch_bounds__(NT, 1) __cluster_dims__(CSZ, 1, 1)
void rvnn_cluster16(const float* __restrict__ h,      // [B,N,FI]
                    const float* __restrict__ W_emb,  // [FO,FI]
                    const float* __restrict__ W_fc,   // [2,FO]
                    const float* __restrict__ b_fc,   // [2]
                    float* __restrict__ y)            // [B,2]
{
    __shared__ float4 s_part[NOG][2][FQ];  // per-o-group V partials (12 KB)
    __shared__ float4 s_V[2][FQ];
    __shared__ float4 s_h[B_][FQ + 1];     // pad: rotate banks across b
    __shared__ float  s_red[CSZ][64];      // rank 0 receives all partials

    cg::cluster_group cluster = cg::this_cluster();
    const unsigned rank = cluster.block_rank();
    const int t  = threadIdx.x;
    const int g  = t / FQ;                 // o-group 0..31 (4 o's each)
    const int fq = t % FQ;                 // f-quad within slice 0..11

    const float4* wemb4 = reinterpret_cast<const float4*>(W_emb);

    // ---- Front-batch every global access into one latency round ----
    const float bf = __ldg(&b_fc[t & 1]);

    // h staging: exactly one quad per thread (384 = 32 b x 12 q).
    const int hb = t / FQ, hq = t % FQ;
    float4 hv = __ldg(reinterpret_cast<const float4*>(
                    h + (size_t)hb * N_ * FI_ + rank * FS) + hq);

    float4 w[4];                           // this thread's 4 W_emb quads
    float  f0[4], f1[4];
    #pragma unroll
    for (int j = 0; j < 4; ++j) {
        const int o = g * 4 + j;
        w[j]  = __ldg(&wemb4[(size_t)o * (FI_/4) + rank * FQ + fq]);
        f0[j] = __ldg(&W_fc[o]);
        f1[j] = __ldg(&W_fc[FO_ + o]);
    }

    // ---- Phase 1: V partials (pure FMA on registers) ----
    float4 a0 = make_float4(0.f, 0.f, 0.f, 0.f);
    float4 a1 = make_float4(0.f, 0.f, 0.f, 0.f);
    #pragma unroll
    for (int j = 0; j < 4; ++j) {
        a0.x = fmaf(f0[j], w[j].x, a0.x); a0.y = fmaf(f0[j], w[j].y, a0.y);
        a0.z = fmaf(f0[j], w[j].z, a0.z); a0.w = fmaf(f0[j], w[j].w, a0.w);
        a1.x = fmaf(f1[j], w[j].x, a1.x); a1.y = fmaf(f1[j], w[j].y, a1.y);
        a1.z = fmaf(f1[j], w[j].z, a1.z); a1.w = fmaf(f1[j], w[j].w, a1.w);
    }
    s_part[g][0][fq] = a0;
    s_part[g][1][fq] = a1;
    s_h[hb][hq] = hv;
    __syncthreads();

    // ---- Fold 32 o-group partials into V slice ----
    if (t < 2 * FQ) {
        const int c = t / FQ, q = t % FQ;
        float4 s = make_float4(0.f, 0.f, 0.f, 0.f);
        #pragma unroll
        for (int k = 0; k < NOG; ++k) {
            float4 p = s_part[k][c][q];
            s.x += p.x; s.y += p.y; s.z += p.z; s.w += p.w;
        }
        s_V[c][q] = s;
    }
    __syncthreads();

    // ---- Phase 2: partial y[b,c] over this CTA's 12 quads; PUSH to rank 0 ----
    if (t < 64) {
        const int b = t >> 1, c = t & 1;
        float acc = 0.f;
        #pragma unroll
        for (int q = 0; q < FQ; ++q) {
            float4 hq4 = s_h[b][q];
            float4 vv  = s_V[c][q];
            acc = fmaf(hq4.x, vv.x, fmaf(hq4.y, vv.y,
                  fmaf(hq4.z, vv.z, fmaf(hq4.w, vv.w, acc))));
        }
        float* dst = cluster.map_shared_rank(&s_red[rank][0], 0);
        dst[t] = acc;                      // remote ST (local if rank==0)
    }

    // ---- ONE cluster barrier: arrive.release orders the DSMEM stores ----
    cluster.sync();

    if (rank == 0 && t < 64) {
        float total = 0.f;
        #pragma unroll
        for (int r = 0; r < CSZ; ++r)
            total += s_red[r][t];
        y[t] = total + bf;
    }
}

extern "C" void kernel_launch(void* const* d_in, const int* in_sizes, int n_in,
                              void* d_out, int out_size)
{
    // metadata order: h, adj, W_emb, W_ioux, b_ioux, W_iouh, b_iouh,
    //                 W_coux, b_coux, W_couh, b_couh, W_fc, b_fc
    const float* h     = (const float*)d_in[0];
    const float* W_emb = (const float*)d_in[2];
    const float* W_fc  = (const float*)d_in[11];
    const float* b_fc  = (const float*)d_in[12];
    float* y = (float*)d_out;

    // Cluster size 16 exceeds the portable max (8): opt in once (host-side
    // attribute, no device memory, idempotent).
    static bool attr_set = false;
    if (!attr_set) {
        cudaFuncSetAttribute(rvnn_cluster16,
                             cudaFuncAttributeNonPortableClusterSizeAllowed, 1);
        attr_set = true;
    }

    rvnn_cluster16<<<CSZ, NT>>>(h, W_emb, W_fc, b_fc, y);
}